// round 3
// baseline (speedup 1.0000x reference)
#include <cuda_runtime.h>
#include <cuda_fp16.h>
#include <cstdint>

// ============================================================================
// CIN fused kernel, GB300 sm_103 (baseline PTX path: mma.sync + ldmatrix).
// Per CTA (4 batches): out[n,o] = sum_k Zt[n,k] * W[o,k],  k=(h,m), n=(bl,d)
//   A = Zt built in REGISTERS (fp32 product -> fp16, single rounding)
//   B = W chunk (fp16, pre-converted) via cp.async + ldmatrix
// Warp tile: 16 rows x 128 o, acc 64 regs. Grid 128 x 512 threads.
// ============================================================================

#define DEVINL __device__ __forceinline__

constexpr int THREADS = 512;
constexpr int NCTA    = 128;
constexpr int NCHUNK  = 32 + 128 + 128;   // 288 k-chunks of 32

// smem layout (bytes)
constexpr int SM_SCORE = 0;        // 4 floats
constexpr int SM_BIAS  = 64;       // 384 floats
constexpr int SM_LW    = 64 + 1536;            // 384 floats -> ends 3136
constexpr int SM_W     = 3200;                 // 2 x (128 rows x 80B) = 20480
constexpr int SM_X0    = SM_W + 20480;         // 16 pair-rows x (256*8 + 16) = 33024
constexpr int X0_ROW   = 2064;
constexpr int SM_H     = SM_X0 + 33024;        // 256 n-rows x 528B = 135168
constexpr int H_ROW    = 528;
constexpr int SMEM_BYTES = SM_H + 256 * H_ROW; // 191872

// device scratch: fp16 weights
__device__ __align__(16) __half g_W0h[128 * 1024];
__device__ __align__(16) __half g_W1h[128 * 4096];
__device__ __align__(16) __half g_W2h[128 * 4096];

// ---------------- helpers ----------------
DEVINL uint32_t smem_u32(const void* p) {
    uint32_t a;
    asm("{ .reg .u64 t; cvta.to.shared.u64 t, %1; cvt.u32.u64 %0, t; }"
        : "=r"(a) : "l"(p));
    return a;
}

DEVINL void cp_async16(uint32_t dst, const void* src) {
    asm volatile("cp.async.cg.shared.global [%0], [%1], 16;"
                 :: "r"(dst), "l"(src) : "memory");
}
DEVINL void cp_commit() { asm volatile("cp.async.commit_group;" ::: "memory"); }
DEVINL void cp_wait0()  { asm volatile("cp.async.wait_group 0;" ::: "memory"); }

DEVINL uint32_t pack_h2(float lo, float hi) {
    uint32_t r;
    asm("cvt.rn.f16x2.f32 %0, %1, %2;" : "=r"(r) : "f"(hi), "f"(lo));
    return r;
}

DEVINL void ldsm_x4(uint32_t& b0, uint32_t& b1, uint32_t& b2, uint32_t& b3,
                    uint32_t addr) {
    asm volatile("ldmatrix.sync.aligned.m8n8.x4.shared.b16 {%0,%1,%2,%3}, [%4];"
                 : "=r"(b0), "=r"(b1), "=r"(b2), "=r"(b3) : "r"(addr));
}

DEVINL void mma16816(float* c, uint32_t a0, uint32_t a1, uint32_t a2, uint32_t a3,
                     uint32_t b0, uint32_t b1) {
    asm volatile(
        "mma.sync.aligned.m16n8k16.row.col.f32.f16.f16.f32 "
        "{%0,%1,%2,%3}, {%4,%5,%6,%7}, {%8,%9}, {%0,%1,%2,%3};"
        : "+f"(c[0]), "+f"(c[1]), "+f"(c[2]), "+f"(c[3])
        : "r"(a0), "r"(a1), "r"(a2), "r"(a3), "r"(b0), "r"(b1));
}

// ============================================================================
// prep: fp32 W -> fp16 scratch
// ============================================================================
__global__ void cin_w2h(const float* __restrict__ W0,
                        const float* __restrict__ W1,
                        const float* __restrict__ W2) {
    int i = blockIdx.x * blockDim.x + threadIdx.x;
    constexpr int S0 = 128 * 1024;
    constexpr int S1 = 128 * 4096;
    if (i < S0)               g_W0h[i] = __float2half_rn(W0[i]);
    else if (i < S0 + S1)     g_W1h[i - S0] = __float2half_rn(W1[i - S0]);
    else if (i < S0 + 2 * S1) g_W2h[i - S0 - S1] = __float2half_rn(W2[i - S0 - S1]);
}

// ============================================================================
// main fused kernel
// ============================================================================
DEVINL void issue_w(int gc, uint32_t wdst, int tid) {
    const __half* src; int kw;
    if (gc < 32)       { src = g_W0h + gc * 32;          kw = 1024; }
    else if (gc < 160) { src = g_W1h + (gc - 32) * 32;   kw = 4096; }
    else               { src = g_W2h + (gc - 160) * 32;  kw = 4096; }
    int r = tid >> 2, j = tid & 3;
    cp_async16(wdst + (uint32_t)r * 80 + (uint32_t)j * 16,
               src + (size_t)r * kw + j * 8);
    cp_commit();
}

__global__ __launch_bounds__(THREADS, 1)
void cin_main(const float* __restrict__ x0g,
              const float* __restrict__ bias0,
              const float* __restrict__ bias1,
              const float* __restrict__ bias2,
              const float* __restrict__ lwp,
              const float* __restrict__ lbp,
              float* __restrict__ outp) {
    extern __shared__ char smemc[];
    const uint32_t sb = smem_u32(smemc);
    const int tid  = threadIdx.x;
    const int w    = tid >> 5;
    const int lane = tid & 31;
    const int b_base = blockIdx.x * 4;

    // prefetch first W chunk immediately
    issue_w(0, sb + SM_W, tid);

    // bias / lw to smem
    {
        const float* bptrs[3] = { bias0, bias1, bias2 };
        float* biasS = (float*)(smemc + SM_BIAS);
        float* lwS   = (float*)(smemc + SM_LW);
        for (int i = tid; i < 384; i += THREADS) {
            biasS[i] = bptrs[i >> 7][i & 127];
            lwS[i]   = lwp[i];
        }
    }
    if (tid < 4) ((float*)(smemc + SM_SCORE))[tid] = 0.0f;

    // x0 pairs: x0s[p][n] = {x0[bl][2p][d], x0[bl][2p+1][d]},  n = bl*64+d
    for (int idx = tid; idx < 16 * 256; idx += THREADS) {
        int p = idx >> 8, n = idx & 255;
        int blx = n >> 6, dx = n & 63;
        const float* src = x0g + ((size_t)(b_base + blx) * 32 + 2 * p) * 64 + dx;
        float2 v; v.x = src[0]; v.y = src[64];
        *(float2*)(smemc + SM_X0 + p * X0_ROW + n * 8) = v;
    }
    __syncthreads();
    // h init (layer 0): h[n][m] = x0 pair values, m = 0..31
    for (int idx = tid; idx < 16 * 256; idx += THREADS) {
        int p = idx >> 8, n = idx & 255;
        float2 v = *(const float2*)(smemc + SM_X0 + p * X0_ROW + n * 8);
        float* hrow = (float*)(smemc + SM_H + (size_t)n * H_ROW);
        hrow[2 * p] = v.x; hrow[2 * p + 1] = v.y;
    }

    // per-thread geometry
    const int q  = lane & 3;
    const int n0 = 16 * w + (lane >> 2);
    const int n1 = n0 + 8;
    const int blw = w >> 2;
    const int mi = lane >> 3;
    const uint32_t lm_base = (uint32_t)(((mi >> 1) * 8 + (lane & 7)) * 80 +
                                        (mi & 1) * 16);

    float acc[16][4];
#pragma unroll
    for (int t = 0; t < 16; t++)
#pragma unroll
        for (int c = 0; c < 4; c++) acc[t][c] = 0.0f;

    float score = 0.0f;
    int gc = 0;

    for (int lay = 0; lay < 3; lay++) {
        const int nh = (lay == 0) ? 32 : 128;
        for (int hh = 0; hh < nh; hh++, gc++) {
            const int buf = gc & 1;
            cp_wait0();
            __syncthreads();                 // W[buf] visible; prev compute done
            if (gc + 1 < NCHUNK)
                issue_w(gc + 1, sb + SM_W + (uint32_t)(buf ^ 1) * 10240u, tid);

            const uint32_t wbu = sb + SM_W + (uint32_t)buf * 10240u;
            const float hv0 = *(const float*)(smemc + SM_H + (size_t)n0 * H_ROW + hh * 4);
            const float hv1 = *(const float*)(smemc + SM_H + (size_t)n1 * H_ROW + hh * 4);

#pragma unroll
            for (int s = 0; s < 2; s++) {
                const int p = 8 * s + q;
                float2 x00 = *(const float2*)(smemc + SM_X0 + p * X0_ROW + n0 * 8);
                float2 x01 = *(const float2*)(smemc + SM_X0 + (p + 4) * X0_ROW + n0 * 8);
                float2 x10 = *(const float2*)(smemc + SM_X0 + p * X0_ROW + n1 * 8);
                float2 x11 = *(const float2*)(smemc + SM_X0 + (p + 4) * X0_ROW + n1 * 8);
                uint32_t a0 = pack_h2(hv0 * x00.x, hv0 * x00.y);
                uint32_t a1 = pack_h2(hv1 * x10.x, hv1 * x10.y);
                uint32_t a2 = pack_h2(hv0 * x01.x, hv0 * x01.y);
                uint32_t a3 = pack_h2(hv1 * x11.x, hv1 * x11.y);
                const uint32_t lma = wbu + lm_base + (uint32_t)s * 32;
#pragma unroll
                for (int g = 0; g < 8; g++) {
                    uint32_t b0, b1, b2, b3;
                    ldsm_x4(b0, b1, b2, b3, lma + (uint32_t)g * 1280);
                    mma16816(acc[2 * g],     a0, a1, a2, a3, b0, b1);
                    mma16816(acc[2 * g + 1], a0, a1, a2, a3, b2, b3);
                }
            }
        }

        // -------- epilogue (register-resident; only own h rows touched) -----
        {
            const float* biasS = (const float*)(smemc + SM_BIAS) + lay * 128;
            const float* lwS   = (const float*)(smemc + SM_LW) + lay * 128;
            float* h0 = (float*)(smemc + SM_H + (size_t)n0 * H_ROW);
            float* h1 = (float*)(smemc + SM_H + (size_t)n1 * H_ROW);
            float sc = 0.0f;
#pragma unroll
            for (int t = 0; t < 16; t++) {
                const int o = 8 * t + 2 * q;
                const float bv0 = biasS[o], bv1 = biasS[o + 1];
                const float lw0 = lwS[o],  lw1 = lwS[o + 1];
                float v00 = fmaxf(acc[t][0] + bv0, 0.0f);
                float v01 = fmaxf(acc[t][1] + bv1, 0.0f);
                float v10 = fmaxf(acc[t][2] + bv0, 0.0f);
                float v11 = fmaxf(acc[t][3] + bv1, 0.0f);
                sc += (v00 + v10) * lw0 + (v01 + v11) * lw1;
                if (lay < 2) {
                    *(float2*)(h0 + o) = make_float2(v00, v01);
                    *(float2*)(h1 + o) = make_float2(v10, v11);
                }
                acc[t][0] = acc[t][1] = acc[t][2] = acc[t][3] = 0.0f;
            }
            score += sc;
        }
    }

    // warp-reduce score, accumulate per-batch
#pragma unroll
    for (int off = 16; off; off >>= 1)
        score += __shfl_xor_sync(0xFFFFFFFFu, score, off);
    if (lane == 0) atomicAdd((float*)(smemc + SM_SCORE) + blw, score);
    __syncthreads();

    if (tid < 4) outp[b_base + tid] = ((float*)(smemc + SM_SCORE))[tid] + lbp[0];
}

extern "C" void kernel_launch(void* const* d_in, const int* in_sizes, int n_in,
                              void* d_out, int out_size) {
    const float* x0 = (const float*)d_in[0];
    const float* W0 = (const float*)d_in[1];
    const float* b0 = (const float*)d_in[2];
    const float* W1 = (const float*)d_in[3];
    const float* b1 = (const float*)d_in[4];
    const float* W2 = (const float*)d_in[5];
    const float* b2 = (const float*)d_in[6];
    const float* lw = (const float*)d_in[7];
    const float* lb = (const float*)d_in[8];
    float* outp = (float*)d_out;

    constexpr int TOTW = 128 * (1024 + 4096 + 4096);
    cin_w2h<<<(TOTW + 1023) / 1024, 1024>>>(W0, W1, W2);

    static_assert(SMEM_BYTES <= 227 * 1024, "smem");
    cudaFuncSetAttribute(cin_main, cudaFuncAttributeMaxDynamicSharedMemorySize,
                         SMEM_BYTES);
    cin_main<<<NCTA, THREADS, SMEM_BYTES>>>(x0, b0, b1, b2, lw, lb, outp);
}

// round 4
// speedup vs baseline: 1.4127x; 1.4127x over previous
#include <cuda_runtime.h>
#include <cuda_fp16.h>
#include <cstdint>

// ============================================================================
// CIN fused kernel, GB300 sm_103 (mma.sync + ldmatrix path; tcgen05 is not
// available under the harness's plain sm_103 ptxas target).
// Per CTA (4 batches): out[n,o] = sum_k Zt[n,k] * W[o,k],  k=(h,m), n=(bl,d)
//   A = Zt built in REGISTERS from register-resident x0 (fp32 mul -> fp16)
//   B = W chunk (fp16 scratch) via cp.async + ldmatrix, double buffered
// Warp tile: 32 n-rows x 64 o (o split across warp halves -> B reuse x2).
// ============================================================================

#define DEVINL __device__ __forceinline__

constexpr int THREADS = 512;
constexpr int NCTA    = 128;
constexpr int NCHUNK  = 32 + 128 + 128;   // 288 k-chunks of 32

// smem layout (bytes)
constexpr int SM_SCORE = 0;                    // 4 floats
constexpr int SM_BIAS  = 64;                   // 384 floats
constexpr int SM_LW    = 1600;                 // 384 floats
constexpr int SM_W     = 3200;                 // 2 x (128 rows x 80B) = 20480
constexpr int SM_H     = SM_W + 20480;         // 256 rows x 132 floats
constexpr int H_ROWF   = 132;                  // floats per h row (pad vs 128)
constexpr int SMEM_BYTES = SM_H + 256 * H_ROWF * 4;   // 158848

// device scratch: fp16 weights
__device__ __align__(16) __half g_W0h[128 * 1024];
__device__ __align__(16) __half g_W1h[128 * 4096];
__device__ __align__(16) __half g_W2h[128 * 4096];

// ---------------- helpers ----------------
DEVINL uint32_t smem_u32(const void* p) {
    uint32_t a;
    asm("{ .reg .u64 t; cvta.to.shared.u64 t, %1; cvt.u32.u64 %0, t; }"
        : "=r"(a) : "l"(p));
    return a;
}

DEVINL void cp_async16(uint32_t dst, const void* src) {
    asm volatile("cp.async.cg.shared.global [%0], [%1], 16;"
                 :: "r"(dst), "l"(src) : "memory");
}
DEVINL void cp_commit() { asm volatile("cp.async.commit_group;" ::: "memory"); }
DEVINL void cp_wait0()  { asm volatile("cp.async.wait_group 0;" ::: "memory"); }

DEVINL uint32_t pack_h2(float lo, float hi) {
    uint32_t r;
    asm("cvt.rn.f16x2.f32 %0, %1, %2;" : "=r"(r) : "f"(hi), "f"(lo));
    return r;
}

DEVINL void ldsm_x4(uint32_t& b0, uint32_t& b1, uint32_t& b2, uint32_t& b3,
                    uint32_t addr) {
    asm volatile("ldmatrix.sync.aligned.m8n8.x4.shared.b16 {%0,%1,%2,%3}, [%4];"
                 : "=r"(b0), "=r"(b1), "=r"(b2), "=r"(b3) : "r"(addr));
}

DEVINL void mma16816(float* c, uint32_t a0, uint32_t a1, uint32_t a2, uint32_t a3,
                     uint32_t b0, uint32_t b1) {
    asm volatile(
        "mma.sync.aligned.m16n8k16.row.col.f32.f16.f16.f32 "
        "{%0,%1,%2,%3}, {%4,%5,%6,%7}, {%8,%9}, {%0,%1,%2,%3};"
        : "+f"(c[0]), "+f"(c[1]), "+f"(c[2]), "+f"(c[3])
        : "r"(a0), "r"(a1), "r"(a2), "r"(a3), "r"(b0), "r"(b1));
}

// ============================================================================
// prep: fp32 W -> fp16 scratch
// ============================================================================
__global__ void cin_w2h(const float* __restrict__ W0,
                        const float* __restrict__ W1,
                        const float* __restrict__ W2) {
    int i = blockIdx.x * blockDim.x + threadIdx.x;
    constexpr int S0 = 128 * 1024;
    constexpr int S1 = 128 * 4096;
    if (i < S0)               g_W0h[i] = __float2half_rn(W0[i]);
    else if (i < S0 + S1)     g_W1h[i - S0] = __float2half_rn(W1[i - S0]);
    else if (i < S0 + 2 * S1) g_W2h[i - S0 - S1] = __float2half_rn(W2[i - S0 - S1]);
}

DEVINL void issue_w(int gc, uint32_t wdst, int tid) {
    const __half* src; int kw;
    if (gc < 32)       { src = g_W0h + gc * 32;          kw = 1024; }
    else if (gc < 160) { src = g_W1h + (gc - 32) * 32;   kw = 4096; }
    else               { src = g_W2h + (gc - 160) * 32;  kw = 4096; }
    int r = tid >> 2, j = tid & 3;
    cp_async16(wdst + (uint32_t)r * 80 + (uint32_t)j * 16,
               src + (size_t)r * kw + j * 8);
    cp_commit();
}

// ============================================================================
// main fused kernel: 1 CTA = 4 batches (256 n-rows x 128 o), 3 layers + score
// ============================================================================
__global__ __launch_bounds__(THREADS, 1)
void cin_main(const float* __restrict__ x0g,
              const float* __restrict__ bias0,
              const float* __restrict__ bias1,
              const float* __restrict__ bias2,
              const float* __restrict__ lwp,
              const float* __restrict__ lbp,
              float* __restrict__ outp) {
    extern __shared__ char smemc[];
    const uint32_t sb = smem_u32(smemc);
    const int tid  = threadIdx.x;
    const int w    = tid >> 5;
    const int lane = tid & 31;
    const int b_base = blockIdx.x * 4;

    // prefetch first W chunk immediately
    issue_w(0, sb + SM_W, tid);

    // bias / lw to smem
    {
        const float* bptrs[3] = { bias0, bias1, bias2 };
        float* biasS = (float*)(smemc + SM_BIAS);
        float* lwS   = (float*)(smemc + SM_LW);
        for (int i = tid; i < 384; i += THREADS) {
            biasS[i] = bptrs[i >> 7][i & 127];
            lwS[i]   = lwp[i];
        }
    }
    if (tid < 4) ((float*)(smemc + SM_SCORE))[tid] = 0.0f;

    float* hS = (float*)(smemc + SM_H);
    // layer-0 h: h[n][m] = x0[bl][m][d],  n = bl*64 + d
    for (int i = tid; i < 256 * 32; i += THREADS) {
        int m = i >> 8, n = i & 255;
        hS[(size_t)n * H_ROWF + m] =
            x0g[(((size_t)(b_base + (n >> 6))) * 32 + m) * 64 + (n & 63)];
    }

    // ---- per-thread geometry: warp = (wn, wo); thread rows n_j, o-subset ----
    const int wn = w & 7;           // n block (32 rows)
    const int wo = w >> 3;          // o half (64 outputs)
    const int r  = lane >> 2;
    const int q  = lane & 3;
    const int bl = wn >> 1;
    const int dbase = ((wn & 1) << 5) + r;     // d of row j=0

    // x0 registers: x0r[j][i] = {x0[bl][2q+8i][d_j], x0[bl][2q+8i+1][d_j]}
    float2 x0r[4][4];
    {
        const float* xb = x0g + ((size_t)(b_base + bl) * 32) * 64;
#pragma unroll
        for (int j = 0; j < 4; j++) {
            int dj = dbase + 8 * j;
#pragma unroll
            for (int i = 0; i < 4; i++) {
                int m = 2 * q + 8 * i;
                x0r[j][i] = make_float2(xb[(size_t)m * 64 + dj],
                                        xb[(size_t)(m + 1) * 64 + dj]);
            }
        }
    }

    // h row pointers (rows n_j = 32*wn + r + 8j)
    float* hrow0 = hS + (size_t)(32 * wn + r)      * H_ROWF;
    float* hrow1 = hrow0 + 8 * H_ROWF;
    float* hrow2 = hrow0 + 16 * H_ROWF;
    float* hrow3 = hrow0 + 24 * H_ROWF;

    // ldmatrix fragment base (within this warp's 64-o half)
    const int mi = lane >> 3;
    const uint32_t lm_base = (uint32_t)(wo * 5120 +
                             ((mi >> 1) * 8 + (lane & 7)) * 80 + (mi & 1) * 16);

    float acc[16][4];
#pragma unroll
    for (int t = 0; t < 16; t++)
#pragma unroll
        for (int c = 0; c < 4; c++) acc[t][c] = 0.0f;

    float score = 0.0f;
    int gc = 0;
    __syncthreads();   // h init + score init visible

    for (int lay = 0; lay < 3; lay++) {
        const int nh = (lay == 0) ? 32 : 128;
        for (int hh = 0; hh < nh; hh++, gc++) {
            const int buf = gc & 1;
            cp_wait0();
            __syncthreads();                 // W[buf] visible; prev uses done
            if (gc + 1 < NCHUNK)
                issue_w(gc + 1, sb + SM_W + (uint32_t)(buf ^ 1) * 10240u, tid);

            const uint32_t wbu = sb + SM_W + (uint32_t)buf * 10240u + lm_base;
            const float hv0 = hrow0[hh];
            const float hv1 = hrow1[hh];
            const float hv2 = hrow2[hh];
            const float hv3 = hrow3[hh];

#pragma unroll
            for (int s = 0; s < 2; s++) {
                // A fragments, row-tile 0 (rows j0,j1) and 1 (rows j2,j3)
                uint32_t a00 = pack_h2(hv0 * x0r[0][2*s].x,   hv0 * x0r[0][2*s].y);
                uint32_t a01 = pack_h2(hv1 * x0r[1][2*s].x,   hv1 * x0r[1][2*s].y);
                uint32_t a02 = pack_h2(hv0 * x0r[0][2*s+1].x, hv0 * x0r[0][2*s+1].y);
                uint32_t a03 = pack_h2(hv1 * x0r[1][2*s+1].x, hv1 * x0r[1][2*s+1].y);
                uint32_t a10 = pack_h2(hv2 * x0r[2][2*s].x,   hv2 * x0r[2][2*s].y);
                uint32_t a11 = pack_h2(hv3 * x0r[3][2*s].x,   hv3 * x0r[3][2*s].y);
                uint32_t a12 = pack_h2(hv2 * x0r[2][2*s+1].x, hv2 * x0r[2][2*s+1].y);
                uint32_t a13 = pack_h2(hv3 * x0r[3][2*s+1].x, hv3 * x0r[3][2*s+1].y);
                const uint32_t lma = wbu + (uint32_t)s * 32;
#pragma unroll
                for (int g = 0; g < 4; g++) {
                    uint32_t b0, b1, b2, b3;
                    ldsm_x4(b0, b1, b2, b3, lma + (uint32_t)g * 1280);
                    mma16816(acc[2*g],      a00, a01, a02, a03, b0, b1);
                    mma16816(acc[2*g + 1],  a00, a01, a02, a03, b2, b3);
                    mma16816(acc[8 + 2*g],     a10, a11, a12, a13, b0, b1);
                    mma16816(acc[8 + 2*g + 1], a10, a11, a12, a13, b2, b3);
                }
            }
        }

        // -------- epilogue --------
        __syncthreads();   // all warps done reading h for this layer
        {
            const float* biasS = (const float*)(smemc + SM_BIAS) + lay * 128;
            const float* lwS   = (const float*)(smemc + SM_LW) + lay * 128;
            float sc = 0.0f;
#pragma unroll
            for (int T = 0; T < 2; T++) {
                float* ha = T ? hrow2 : hrow0;
                float* hb = T ? hrow3 : hrow1;
#pragma unroll
                for (int go = 0; go < 8; go++) {
                    const int t = 8 * T + go;
                    const int o = 64 * wo + 8 * go + 2 * q;
                    const float bv0 = biasS[o], bv1 = biasS[o + 1];
                    float v00 = fmaxf(acc[t][0] + bv0, 0.0f);
                    float v01 = fmaxf(acc[t][1] + bv1, 0.0f);
                    float v10 = fmaxf(acc[t][2] + bv0, 0.0f);
                    float v11 = fmaxf(acc[t][3] + bv1, 0.0f);
                    sc += (v00 + v10) * lwS[o] + (v01 + v11) * lwS[o + 1];
                    if (lay < 2) {
                        *(float2*)(ha + o) = make_float2(v00, v01);
                        *(float2*)(hb + o) = make_float2(v10, v11);
                    }
                    acc[t][0] = acc[t][1] = acc[t][2] = acc[t][3] = 0.0f;
                }
            }
            score += sc;
        }
    }

    // warp-reduce score, accumulate per-batch
#pragma unroll
    for (int off = 16; off; off >>= 1)
        score += __shfl_xor_sync(0xFFFFFFFFu, score, off);
    if (lane == 0) atomicAdd((float*)(smemc + SM_SCORE) + bl, score);
    __syncthreads();

    if (tid < 4) outp[b_base + tid] = ((float*)(smemc + SM_SCORE))[tid] + lbp[0];
}

extern "C" void kernel_launch(void* const* d_in, const int* in_sizes, int n_in,
                              void* d_out, int out_size) {
    const float* x0 = (const float*)d_in[0];
    const float* W0 = (const float*)d_in[1];
    const float* b0 = (const float*)d_in[2];
    const float* W1 = (const float*)d_in[3];
    const float* b1 = (const float*)d_in[4];
    const float* W2 = (const float*)d_in[5];
    const float* b2 = (const float*)d_in[6];
    const float* lw = (const float*)d_in[7];
    const float* lb = (const float*)d_in[8];
    float* outp = (float*)d_out;

    constexpr int TOTW = 128 * (1024 + 4096 + 4096);
    cin_w2h<<<(TOTW + 1023) / 1024, 1024>>>(W0, W1, W2);

    static_assert(SMEM_BYTES <= 227 * 1024, "smem");
    cudaFuncSetAttribute(cin_main, cudaFuncAttributeMaxDynamicSharedMemorySize,
                         SMEM_BYTES);
    cin_main<<<NCTA, THREADS, SMEM_BYTES>>>(x0, b0, b1, b2, lw, lb, outp);
}

// round 5
// speedup vs baseline: 1.5667x; 1.1090x over previous
#include <cuda_runtime.h>
#include <cuda_fp16.h>
#include <cstdint>

// ============================================================================
// CIN fused kernel, GB300 sm_103 (mma.sync + ldmatrix path).
// Per CTA (4 batches): out[n,o] = sum_k Zt[n,k] * W[o,k],  k=(h,m), n=(bl,d)
//   A = Zt built in REGISTERS: half2 x0 (resident) * h broadcast via HMUL2
//   B = W chunk (fp16 scratch) via cp.async + ldmatrix, double buffered
// K-chunk = 64 (two h rows per barrier round).  Warp tile: 32 n x 64 o.
// ============================================================================

#define DEVINL __device__ __forceinline__

constexpr int THREADS = 512;
constexpr int NCTA    = 128;
constexpr int NCH64   = 16 + 64 + 64;     // 144 k-chunks of 64

// smem layout (bytes)
constexpr int SM_SCORE = 0;                    // 4 floats
constexpr int SM_BIAS  = 64;                   // 384 floats
constexpr int SM_LW    = 1600;                 // 384 floats
constexpr int SM_W     = 3200;                 // 2 stages x 20480
constexpr int W_STAGE  = 20480;                // 2 sub-chunks x (128 rows x 80B)
constexpr int SM_H     = SM_W + 2 * W_STAGE;   // 44160
constexpr int H_ROWF   = 132;                  // floats per h row (pad)
constexpr int SMEM_BYTES = SM_H + 256 * H_ROWF * 4;   // 179328

// device scratch: fp16 weights
__device__ __align__(16) __half g_W0h[128 * 1024];
__device__ __align__(16) __half g_W1h[128 * 4096];
__device__ __align__(16) __half g_W2h[128 * 4096];

// ---------------- helpers ----------------
DEVINL uint32_t smem_u32(const void* p) {
    uint32_t a;
    asm("{ .reg .u64 t; cvta.to.shared.u64 t, %1; cvt.u32.u64 %0, t; }"
        : "=r"(a) : "l"(p));
    return a;
}

DEVINL void cp_async16(uint32_t dst, const void* src) {
    asm volatile("cp.async.cg.shared.global [%0], [%1], 16;"
                 :: "r"(dst), "l"(src) : "memory");
}
DEVINL void cp_commit() { asm volatile("cp.async.commit_group;" ::: "memory"); }
DEVINL void cp_wait0()  { asm volatile("cp.async.wait_group 0;" ::: "memory"); }

DEVINL uint32_t h2u(__half2 v) { return *reinterpret_cast<uint32_t*>(&v); }

DEVINL void ldsm_x4(uint32_t& b0, uint32_t& b1, uint32_t& b2, uint32_t& b3,
                    uint32_t addr) {
    asm volatile("ldmatrix.sync.aligned.m8n8.x4.shared.b16 {%0,%1,%2,%3}, [%4];"
                 : "=r"(b0), "=r"(b1), "=r"(b2), "=r"(b3) : "r"(addr));
}

DEVINL void mma16816(float* c, uint32_t a0, uint32_t a1, uint32_t a2, uint32_t a3,
                     uint32_t b0, uint32_t b1) {
    asm volatile(
        "mma.sync.aligned.m16n8k16.row.col.f32.f16.f16.f32 "
        "{%0,%1,%2,%3}, {%4,%5,%6,%7}, {%8,%9}, {%0,%1,%2,%3};"
        : "+f"(c[0]), "+f"(c[1]), "+f"(c[2]), "+f"(c[3])
        : "r"(a0), "r"(a1), "r"(a2), "r"(a3), "r"(b0), "r"(b1));
}

// ============================================================================
// prep: fp32 W -> fp16 scratch
// ============================================================================
__global__ void cin_w2h(const float* __restrict__ W0,
                        const float* __restrict__ W1,
                        const float* __restrict__ W2) {
    int i = blockIdx.x * blockDim.x + threadIdx.x;
    constexpr int S0 = 128 * 1024;
    constexpr int S1 = 128 * 4096;
    if (i < S0)               g_W0h[i] = __float2half_rn(W0[i]);
    else if (i < S0 + S1)     g_W1h[i - S0] = __float2half_rn(W1[i - S0]);
    else if (i < S0 + 2 * S1) g_W2h[i - S0 - S1] = __float2half_rn(W2[i - S0 - S1]);
}

// W chunk-64 fetch: 2 sub-chunks of 32 k-cols; thread -> row tid>>2, 16B seg tid&3
DEVINL void issue_w64(int gc, uint32_t wdst, int tid) {
    const __half* src; int kw;
    if (gc < 16)      { src = g_W0h + gc * 64;         kw = 1024; }
    else if (gc < 80) { src = g_W1h + (gc - 16) * 64;  kw = 4096; }
    else              { src = g_W2h + (gc - 80) * 64;  kw = 4096; }
    int r = tid >> 2, j = tid & 3;
    const __half* s0 = src + (size_t)r * kw + j * 8;
    uint32_t d0 = wdst + (uint32_t)r * 80 + (uint32_t)j * 16;
    cp_async16(d0, s0);
    cp_async16(d0 + 10240u, s0 + 32);
    cp_commit();
}

// ============================================================================
// main fused kernel: 1 CTA = 4 batches (256 n-rows x 128 o), 3 layers + score
// ============================================================================
__global__ __launch_bounds__(THREADS, 1)
void cin_main(const float* __restrict__ x0g,
              const float* __restrict__ bias0,
              const float* __restrict__ bias1,
              const float* __restrict__ bias2,
              const float* __restrict__ lwp,
              const float* __restrict__ lbp,
              float* __restrict__ outp) {
    extern __shared__ char smemc[];
    const uint32_t sb = smem_u32(smemc);
    const int tid  = threadIdx.x;
    const int w    = tid >> 5;
    const int lane = tid & 31;
    const int b_base = blockIdx.x * 4;

    // prefetch first W chunk immediately
    issue_w64(0, sb + SM_W, tid);

    // bias / lw to smem
    {
        const float* bptrs[3] = { bias0, bias1, bias2 };
        float* biasS = (float*)(smemc + SM_BIAS);
        float* lwS   = (float*)(smemc + SM_LW);
        for (int i = tid; i < 384; i += THREADS) {
            biasS[i] = bptrs[i >> 7][i & 127];
            lwS[i]   = lwp[i];
        }
    }
    if (tid < 4) ((float*)(smemc + SM_SCORE))[tid] = 0.0f;

    float* hS = (float*)(smemc + SM_H);
    // layer-0 h: h[n][m] = x0[bl][m][d],  n = bl*64 + d
    for (int i = tid; i < 256 * 32; i += THREADS) {
        int m = i >> 8, n = i & 255;
        hS[(size_t)n * H_ROWF + m] =
            x0g[(((size_t)(b_base + (n >> 6))) * 32 + m) * 64 + (n & 63)];
    }

    // ---- per-thread geometry ----
    const int wn = w & 7;           // n block (32 rows)
    const int wo = w >> 3;          // o half (64 outputs)
    const int r  = lane >> 2;
    const int q  = lane & 3;
    const int bl = wn >> 1;
    const int dbase = ((wn & 1) << 5) + r;

    // x0 as half2 registers: x0h[j][i] = {x0[2q+8i], x0[2q+8i+1]} at d_j
    __half2 x0h[4][4];
    {
        const float* xb = x0g + ((size_t)(b_base + bl) * 32) * 64;
#pragma unroll
        for (int j = 0; j < 4; j++) {
            int dj = dbase + 8 * j;
#pragma unroll
            for (int i = 0; i < 4; i++) {
                int m = 2 * q + 8 * i;
                x0h[j][i] = __floats2half2_rn(xb[(size_t)m * 64 + dj],
                                              xb[(size_t)(m + 1) * 64 + dj]);
            }
        }
    }

    // h row pointers (rows n_j = 32*wn + r + 8j)
    float* hrow0 = hS + (size_t)(32 * wn + r) * H_ROWF;
    float* hrow1 = hrow0 + 8 * H_ROWF;
    float* hrow2 = hrow0 + 16 * H_ROWF;
    float* hrow3 = hrow0 + 24 * H_ROWF;

    // ldmatrix fragment base (within this warp's 64-o half)
    const int mi = lane >> 3;
    const uint32_t lm_base = (uint32_t)(wo * 5120 +
                             ((mi >> 1) * 8 + (lane & 7)) * 80 + (mi & 1) * 16);

    float acc[16][4];
#pragma unroll
    for (int t = 0; t < 16; t++)
#pragma unroll
        for (int c = 0; c < 4; c++) acc[t][c] = 0.0f;

    float score = 0.0f;
    int gc = 0;
    __syncthreads();   // h init + score init visible

    for (int lay = 0; lay < 3; lay++) {
        const int nch = (lay == 0) ? 16 : 64;
        for (int ch = 0; ch < nch; ch++, gc++) {
            const int buf = gc & 1;
            cp_wait0();
            __syncthreads();                 // W[buf] visible; prev uses done
            if (gc + 1 < NCH64)
                issue_w64(gc + 1, sb + SM_W + (uint32_t)(buf ^ 1) * W_STAGE, tid);

            const uint32_t wbu = sb + SM_W + (uint32_t)buf * W_STAGE + lm_base;

            // h values for this chunk's two rows (hh = 2ch, 2ch+1), 4 n-rows
            float2 hf0 = *(const float2*)(hrow0 + 2 * ch);
            float2 hf1 = *(const float2*)(hrow1 + 2 * ch);
            float2 hf2 = *(const float2*)(hrow2 + 2 * ch);
            float2 hf3 = *(const float2*)(hrow3 + 2 * ch);
            __half2 hb[4][2];
            hb[0][0] = __half2half2(__float2half_rn(hf0.x));
            hb[0][1] = __half2half2(__float2half_rn(hf0.y));
            hb[1][0] = __half2half2(__float2half_rn(hf1.x));
            hb[1][1] = __half2half2(__float2half_rn(hf1.y));
            hb[2][0] = __half2half2(__float2half_rn(hf2.x));
            hb[2][1] = __half2half2(__float2half_rn(hf2.y));
            hb[3][0] = __half2half2(__float2half_rn(hf3.x));
            hb[3][1] = __half2half2(__float2half_rn(hf3.y));

#pragma unroll
            for (int s = 0; s < 4; s++) {
                const int sub = s >> 1;      // which h row of the pair
                const int sh  = s & 1;       // m half: [0,16) or [16,32)
                uint32_t a00 = h2u(__hmul2(hb[0][sub], x0h[0][2 * sh]));
                uint32_t a01 = h2u(__hmul2(hb[1][sub], x0h[1][2 * sh]));
                uint32_t a02 = h2u(__hmul2(hb[0][sub], x0h[0][2 * sh + 1]));
                uint32_t a03 = h2u(__hmul2(hb[1][sub], x0h[1][2 * sh + 1]));
                uint32_t a10 = h2u(__hmul2(hb[2][sub], x0h[2][2 * sh]));
                uint32_t a11 = h2u(__hmul2(hb[3][sub], x0h[3][2 * sh]));
                uint32_t a12 = h2u(__hmul2(hb[2][sub], x0h[2][2 * sh + 1]));
                uint32_t a13 = h2u(__hmul2(hb[3][sub], x0h[3][2 * sh + 1]));
                const uint32_t lma = wbu + (uint32_t)sub * 10240u +
                                     (uint32_t)sh * 32u;
#pragma unroll
                for (int g = 0; g < 4; g++) {
                    uint32_t b0, b1, b2, b3;
                    ldsm_x4(b0, b1, b2, b3, lma + (uint32_t)g * 1280);
                    mma16816(acc[2 * g],         a00, a01, a02, a03, b0, b1);
                    mma16816(acc[2 * g + 1],     a00, a01, a02, a03, b2, b3);
                    mma16816(acc[8 + 2 * g],     a10, a11, a12, a13, b0, b1);
                    mma16816(acc[8 + 2 * g + 1], a10, a11, a12, a13, b2, b3);
                }
            }
        }

        // -------- epilogue --------
        __syncthreads();   // all warps done reading h for this layer
        {
            const float* biasS = (const float*)(smemc + SM_BIAS) + lay * 128;
            const float* lwS   = (const float*)(smemc + SM_LW) + lay * 128;
            float sc = 0.0f;
#pragma unroll
            for (int T = 0; T < 2; T++) {
                float* ha = T ? hrow2 : hrow0;
                float* hb2 = T ? hrow3 : hrow1;
#pragma unroll
                for (int go = 0; go < 8; go++) {
                    const int t = 8 * T + go;
                    const int o = 64 * wo + 8 * go + 2 * q;
                    const float bv0 = biasS[o], bv1 = biasS[o + 1];
                    float v00 = fmaxf(acc[t][0] + bv0, 0.0f);
                    float v01 = fmaxf(acc[t][1] + bv1, 0.0f);
                    float v10 = fmaxf(acc[t][2] + bv0, 0.0f);
                    float v11 = fmaxf(acc[t][3] + bv1, 0.0f);
                    sc += (v00 + v10) * lwS[o] + (v01 + v11) * lwS[o + 1];
                    if (lay < 2) {
                        *(float2*)(ha + o)  = make_float2(v00, v01);
                        *(float2*)(hb2 + o) = make_float2(v10, v11);
                    }
                    acc[t][0] = acc[t][1] = acc[t][2] = acc[t][3] = 0.0f;
                }
            }
            score += sc;
        }
    }

    // warp-reduce score, accumulate per-batch
#pragma unroll
    for (int off = 16; off; off >>= 1)
        score += __shfl_xor_sync(0xFFFFFFFFu, score, off);
    if (lane == 0) atomicAdd((float*)(smemc + SM_SCORE) + bl, score);
    __syncthreads();

    if (tid < 4) outp[b_base + tid] = ((float*)(smemc + SM_SCORE))[tid] + lbp[0];
}

extern "C" void kernel_launch(void* const* d_in, const int* in_sizes, int n_in,
                              void* d_out, int out_size) {
    const float* x0 = (const float*)d_in[0];
    const float* W0 = (const float*)d_in[1];
    const float* b0 = (const float*)d_in[2];
    const float* W1 = (const float*)d_in[3];
    const float* b1 = (const float*)d_in[4];
    const float* W2 = (const float*)d_in[5];
    const float* b2 = (const float*)d_in[6];
    const float* lw = (const float*)d_in[7];
    const float* lb = (const float*)d_in[8];
    float* outp = (float*)d_out;

    constexpr int TOTW = 128 * (1024 + 4096 + 4096);
    cin_w2h<<<(TOTW + 1023) / 1024, 1024>>>(W0, W1, W2);

    static_assert(SMEM_BYTES <= 227 * 1024, "smem");
    cudaFuncSetAttribute(cin_main, cudaFuncAttributeMaxDynamicSharedMemorySize,
                         SMEM_BYTES);
    cin_main<<<NCTA, THREADS, SMEM_BYTES>>>(x0, b0, b1, b2, lw, lb, outp);
}